// round 1
// baseline (speedup 1.0000x reference)
#include <cuda_runtime.h>
#include <cuda_bf16.h>

#define N_NODES 10000
#define N_EDGES 640000
#define D 128

// ---- scratch (no allocations allowed) ----
__device__ int g_deg[N_NODES];
__device__ int g_off[N_NODES + 1];
__device__ int g_cursor[N_NODES];
__device__ int g_src_sorted[N_EDGES];

// ---------------------------------------------------------------------------
// 1) zero degree histogram
__global__ void zero_deg_kernel() {
    int i = blockIdx.x * blockDim.x + threadIdx.x;
    if (i < N_NODES) g_deg[i] = 0;
}

// 2) histogram of dst
__global__ void hist_kernel(const int* __restrict__ dst) {
    int e = blockIdx.x * blockDim.x + threadIdx.x;
    if (e < N_EDGES) atomicAdd(&g_deg[dst[e]], 1);
}

// 3) single-block exclusive scan over 10000 degrees (1024 threads x 10 chunk)
__global__ void scan_kernel() {
    __shared__ int partial[1024];
    const int t = threadIdx.x;
    const int CHUNK = (N_NODES + 1023) / 1024;  // 10
    const int base = t * CHUNK;

    int s = 0;
    #pragma unroll
    for (int i = 0; i < CHUNK; i++) {
        int n = base + i;
        if (n < N_NODES) s += g_deg[n];
    }
    partial[t] = s;
    __syncthreads();

    // Hillis-Steele inclusive scan
    for (int d = 1; d < 1024; d <<= 1) {
        int v = partial[t];
        int add = (t >= d) ? partial[t - d] : 0;
        __syncthreads();
        partial[t] = v + add;
        __syncthreads();
    }

    int run = (t == 0) ? 0 : partial[t - 1];  // exclusive base
    #pragma unroll
    for (int i = 0; i < CHUNK; i++) {
        int n = base + i;
        if (n < N_NODES) {
            g_off[n] = run;
            g_cursor[n] = run;
            run += g_deg[n];
        }
    }
    if (t == 1023) g_off[N_NODES] = run;  // == N_EDGES
}

// 4) scatter edges into CSR buckets
__global__ void scatter_kernel(const int* __restrict__ src,
                               const int* __restrict__ dst) {
    int e = blockIdx.x * blockDim.x + threadIdx.x;
    if (e < N_EDGES) {
        int pos = atomicAdd(&g_cursor[dst[e]], 1);
        g_src_sorted[pos] = src[e];
    }
}

// ---------------------------------------------------------------------------
// 5) fused: per-node neighbor sum + projection out = h @ W^T + b
//
// Block = 256 threads = 2 nodes per iteration (128 threads each).
// Shared: Wt padded [128][129] (conflict-free LDS both on fill and read)
//         + 2 h rows.
#define WT_STRIDE 129
#define SMEM_BYTES ((D * WT_STRIDE + 2 * D) * 4)

__global__ __launch_bounds__(256, 2)
void fused_agg_proj_kernel(const float* __restrict__ x,
                           const float* __restrict__ W,
                           const float* __restrict__ b,
                           float* __restrict__ out) {
    extern __shared__ float smem[];
    float* sWt = smem;                  // sWt[i*129 + o] = W[o*128 + i]
    float* sh  = smem + D * WT_STRIDE;  // 2 x 128 h rows (16B aligned)

    const int tid  = threadIdx.x;
    const int half = tid >> 7;   // which of the 2 nodes
    const int t    = tid & 127;  // feature / output index

    // stage W transposed into shared (coalesced gmem reads; padded stores)
    for (int idx = tid; idx < D * D; idx += blockDim.x) {
        int o = idx >> 7;
        int i = idx & 127;
        sWt[i * WT_STRIDE + o] = W[idx];
    }
    __syncthreads();

    const float bias = b[t];
    float* hrow = &sh[half * D];

    for (int n0 = blockIdx.x * 2; n0 < N_NODES; n0 += gridDim.x * 2) {
        const int n = n0 + half;
        float acc = 0.f;
        if (n < N_NODES) {
            const int e0 = g_off[n];
            const int e1 = g_off[n + 1];
            int e = e0;
            // unroll-by-4 to raise MLP against L2 latency
            for (; e + 4 <= e1; e += 4) {
                int s0 = g_src_sorted[e + 0];
                int s1 = g_src_sorted[e + 1];
                int s2 = g_src_sorted[e + 2];
                int s3 = g_src_sorted[e + 3];
                float v0 = __ldg(&x[s0 * D + t]);
                float v1 = __ldg(&x[s1 * D + t]);
                float v2 = __ldg(&x[s2 * D + t]);
                float v3 = __ldg(&x[s3 * D + t]);
                acc += v0 + v1 + v2 + v3;
            }
            for (; e < e1; e++) {
                int s = g_src_sorted[e];
                acc += __ldg(&x[s * D + t]);
            }
        }
        hrow[t] = acc;
        __syncthreads();

        if (n < N_NODES) {
            float o_acc = bias;
            #pragma unroll
            for (int i4 = 0; i4 < D / 4; i4++) {
                float4 h4 = *(const float4*)&hrow[i4 * 4];
                o_acc += h4.x * sWt[(i4 * 4 + 0) * WT_STRIDE + t];
                o_acc += h4.y * sWt[(i4 * 4 + 1) * WT_STRIDE + t];
                o_acc += h4.z * sWt[(i4 * 4 + 2) * WT_STRIDE + t];
                o_acc += h4.w * sWt[(i4 * 4 + 3) * WT_STRIDE + t];
            }
            out[n * D + t] = o_acc;
        }
        __syncthreads();
    }
}

// ---------------------------------------------------------------------------
extern "C" void kernel_launch(void* const* d_in, const int* in_sizes, int n_in,
                              void* d_out, int out_size) {
    const float* x   = (const float*)d_in[0];
    const int*   src = (const int*)d_in[1];
    const int*   dst = (const int*)d_in[2];
    const float* W   = (const float*)d_in[3];
    const float* b   = (const float*)d_in[4];
    float* out = (float*)d_out;

    // opt-in to >48KB dynamic smem (idempotent, not a stream op)
    cudaFuncSetAttribute(fused_agg_proj_kernel,
                         cudaFuncAttributeMaxDynamicSharedMemorySize,
                         SMEM_BYTES);

    zero_deg_kernel<<<(N_NODES + 255) / 256, 256>>>();
    hist_kernel<<<(N_EDGES + 255) / 256, 256>>>(dst);
    scan_kernel<<<1, 1024>>>();
    scatter_kernel<<<(N_EDGES + 255) / 256, 256>>>(src, dst);
    fused_agg_proj_kernel<<<296, 256, SMEM_BYTES>>>(x, W, b, out);
}

// round 3
// speedup vs baseline: 1.8413x; 1.8413x over previous
#include <cuda_runtime.h>
#include <cuda_bf16.h>

#define N_NODES 10000
#define N_EDGES 640000
#define D 128

// ---- scratch (no device allocations allowed) ----
__device__ int g_deg[N_NODES];
__device__ int g_off[N_NODES + 1];
__device__ int g_cursor[N_NODES];
__device__ int g_src_sorted[N_EDGES];

// ---------------------------------------------------------------------------
// 1) zero degree histogram (+ pin the sentinel offset)
__global__ void zero_deg_kernel() {
    int i = blockIdx.x * blockDim.x + threadIdx.x;
    if (i < N_NODES) g_deg[i] = 0;
    if (i == 0) g_off[N_NODES] = N_EDGES;
}

// 2) histogram of dst — ILP 8, fire-and-forget atomics (RED)
#define HIST_ILP 8
__global__ void hist_kernel(const int* __restrict__ dst) {
    const int T = N_EDGES / HIST_ILP;  // 80000 threads, coalesced strided
    int t = blockIdx.x * blockDim.x + threadIdx.x;
    if (t >= T) return;
    int d[HIST_ILP];
    #pragma unroll
    for (int k = 0; k < HIST_ILP; k++) d[k] = dst[t + k * T];
    #pragma unroll
    for (int k = 0; k < HIST_ILP; k++) atomicAdd(&g_deg[d[k]], 1);
}

// 3) single-block exclusive scan (shuffle-based, 3 syncs)
__global__ void scan_kernel() {
    __shared__ int warp_sums[32];
    const int t = threadIdx.x;
    const int lane = t & 31, w = t >> 5;
    const int CHUNK = (N_NODES + 1023) / 1024;  // 10
    const int base = t * CHUNK;

    int deg[CHUNK];
    int s = 0;
    #pragma unroll
    for (int i = 0; i < CHUNK; i++) {
        int n = base + i;
        deg[i] = (n < N_NODES) ? g_deg[n] : 0;
        s += deg[i];
    }
    // warp inclusive scan of per-thread sums
    int incl = s;
    #pragma unroll
    for (int d = 1; d < 32; d <<= 1) {
        int v = __shfl_up_sync(0xffffffffu, incl, d);
        if (lane >= d) incl += v;
    }
    if (lane == 31) warp_sums[w] = incl;
    __syncthreads();
    if (w == 0) {
        int v = warp_sums[lane];
        int iv = v;
        #pragma unroll
        for (int d = 1; d < 32; d <<= 1) {
            int u = __shfl_up_sync(0xffffffffu, iv, d);
            if (lane >= d) iv += u;
        }
        warp_sums[lane] = iv;
    }
    __syncthreads();
    int warp_base = (w > 0) ? warp_sums[w - 1] : 0;
    int run = warp_base + (incl - s);  // exclusive base for this thread
    #pragma unroll
    for (int i = 0; i < CHUNK; i++) {
        int n = base + i;
        if (n < N_NODES) {
            g_off[n] = run;
            g_cursor[n] = run;
            run += deg[i];
        }
    }
}

// 4) scatter edges into CSR buckets — ILP 8 to hide ATOMG latency
#define SC_ILP 8
__global__ void scatter_kernel(const int* __restrict__ src,
                               const int* __restrict__ dst) {
    const int T = N_EDGES / SC_ILP;
    int t = blockIdx.x * blockDim.x + threadIdx.x;
    if (t >= T) return;
    int s[SC_ILP], d[SC_ILP];
    #pragma unroll
    for (int k = 0; k < SC_ILP; k++) {
        s[k] = src[t + k * T];
        d[k] = dst[t + k * T];
    }
    int pos[SC_ILP];
    #pragma unroll
    for (int k = 0; k < SC_ILP; k++) pos[k] = atomicAdd(&g_cursor[d[k]], 1);
    #pragma unroll
    for (int k = 0; k < SC_ILP; k++) g_src_sorted[pos[k]] = s[k];
}

// ---------------------------------------------------------------------------
// 5) fused: warp-per-node gather-sum (float4) + 4-node register-blocked
//    projection out = h @ W^T + b.
//
// Block = 256 threads = 8 warps. Each warp owns one group of 4 nodes.
// 10000 nodes = 2500 groups exactly; 313 blocks.
// Shared: sW[i][o] = W[o][i], stride 132 floats (float4-aligned, low-conflict)
//         + per-warp h buffer [4 nodes][128].
#define SW_STRIDE 132
#define SW_FLOATS (D * SW_STRIDE)           // 16896
#define SH_FLOATS (8 * 4 * D)               // 4096
#define SMEM_BYTES ((SW_FLOATS + SH_FLOATS) * 4)  // 83968 B
#define NGROUPS (N_NODES / 4)               // 2500

__global__ __launch_bounds__(256)
void fused_agg_proj_kernel(const float* __restrict__ x,
                           const float* __restrict__ W,
                           const float* __restrict__ b,
                           float* __restrict__ out) {
    extern __shared__ float smem[];
    float* sW = smem;                      // [128][132] transposed W
    float* sh = smem + SW_FLOATS;          // [8 warps][4 nodes][128]

    const int tid  = threadIdx.x;
    const int lane = tid & 31;
    const int wid  = tid >> 5;

    // stage W transposed: coalesced gmem reads; 4-way smem conflict on store
    // (one-time cost, ~64 warp-iterations)
    for (int idx = tid; idx < D * D; idx += 256) {
        int o = idx >> 7;
        int i = idx & 127;
        sW[i * SW_STRIDE + o] = W[idx];
    }
    __syncthreads();

    const int gw = blockIdx.x * 8 + wid;   // warp's node group
    if (gw >= NGROUPS) return;

    float* hbuf = &sh[wid * 4 * D];
    const int n0 = gw * 4;

    // ---- gather: 4 nodes sequentially, whole row per edge via LDG.128 ----
    #pragma unroll
    for (int nn = 0; nn < 4; nn++) {
        const int n = n0 + nn;
        const int e0 = g_off[n];
        const int e1 = g_off[n + 1];

        float4 acc0 = make_float4(0.f, 0.f, 0.f, 0.f);
        float4 acc1 = make_float4(0.f, 0.f, 0.f, 0.f);

        int e = e0;
        while (e + 32 <= e1) {
            int idx = g_src_sorted[e + lane];          // coalesced
            #pragma unroll
            for (int j = 0; j < 32; j += 2) {
                int s0 = __shfl_sync(0xffffffffu, idx, j);
                int s1 = __shfl_sync(0xffffffffu, idx, j + 1);
                float4 v0 = *(const float4*)&x[s0 * D + 4 * lane];
                float4 v1 = *(const float4*)&x[s1 * D + 4 * lane];
                acc0.x += v0.x; acc0.y += v0.y; acc0.z += v0.z; acc0.w += v0.w;
                acc1.x += v1.x; acc1.y += v1.y; acc1.z += v1.z; acc1.w += v1.w;
            }
            e += 32;
        }
        int rem = e1 - e;
        if (rem > 0) {
            int idx = g_src_sorted[e + ((lane < rem) ? lane : 0)];
            for (int j = 0; j < rem; j++) {
                int s = __shfl_sync(0xffffffffu, idx, j);
                float4 v = *(const float4*)&x[s * D + 4 * lane];
                acc0.x += v.x; acc0.y += v.y; acc0.z += v.z; acc0.w += v.w;
            }
        }
        float4 h4 = make_float4(acc0.x + acc1.x, acc0.y + acc1.y,
                                acc0.z + acc1.z, acc0.w + acc1.w);
        *(float4*)&hbuf[nn * D + 4 * lane] = h4;
    }
    __syncwarp();

    // ---- projection: 4-node register blocking; each lane owns 4 outputs ----
    const float* hA = &hbuf[0 * D];
    const float* hB = &hbuf[1 * D];
    const float* hC = &hbuf[2 * D];
    const float* hD = &hbuf[3 * D];

    float4 bias = *(const float4*)&b[4 * lane];
    float4 oA = bias, oB = bias, oC = bias, oD = bias;

    #pragma unroll 8
    for (int i4 = 0; i4 < D / 4; i4++) {
        float ha[4], hb_[4], hc[4], hd[4];
        *(float4*)ha  = *(const float4*)&hA[i4 * 4];   // smem broadcasts
        *(float4*)hb_ = *(const float4*)&hB[i4 * 4];
        *(float4*)hc  = *(const float4*)&hC[i4 * 4];
        *(float4*)hd  = *(const float4*)&hD[i4 * 4];
        #pragma unroll
        for (int k = 0; k < 4; k++) {
            float4 w = *(const float4*)&sW[(i4 * 4 + k) * SW_STRIDE + 4 * lane];
            oA.x += ha[k]  * w.x; oA.y += ha[k]  * w.y; oA.z += ha[k]  * w.z; oA.w += ha[k]  * w.w;
            oB.x += hb_[k] * w.x; oB.y += hb_[k] * w.y; oB.z += hb_[k] * w.z; oB.w += hb_[k] * w.w;
            oC.x += hc[k]  * w.x; oC.y += hc[k]  * w.y; oC.z += hc[k]  * w.z; oC.w += hc[k]  * w.w;
            oD.x += hd[k]  * w.x; oD.y += hd[k]  * w.y; oD.z += hd[k]  * w.z; oD.w += hd[k]  * w.w;
        }
    }

    *(float4*)&out[(n0 + 0) * D + 4 * lane] = oA;
    *(float4*)&out[(n0 + 1) * D + 4 * lane] = oB;
    *(float4*)&out[(n0 + 2) * D + 4 * lane] = oC;
    *(float4*)&out[(n0 + 3) * D + 4 * lane] = oD;
}

// ---------------------------------------------------------------------------
extern "C" void kernel_launch(void* const* d_in, const int* in_sizes, int n_in,
                              void* d_out, int out_size) {
    const float* x   = (const float*)d_in[0];
    const int*   src = (const int*)d_in[1];
    const int*   dst = (const int*)d_in[2];
    const float* W   = (const float*)d_in[3];
    const float* b   = (const float*)d_in[4];
    float* out = (float*)d_out;

    cudaFuncSetAttribute(fused_agg_proj_kernel,
                         cudaFuncAttributeMaxDynamicSharedMemorySize,
                         SMEM_BYTES);

    zero_deg_kernel<<<(N_NODES + 255) / 256, 256>>>();
    hist_kernel<<<(N_EDGES / HIST_ILP + 255) / 256, 256>>>(dst);
    scan_kernel<<<1, 1024>>>();
    scatter_kernel<<<(N_EDGES / SC_ILP + 255) / 256, 256>>>(src, dst);

    const int blocks = (NGROUPS + 7) / 8;  // 313
    fused_agg_proj_kernel<<<blocks, 256, SMEM_BYTES>>>(x, W, b, out);
}

// round 5
// speedup vs baseline: 2.1236x; 1.1533x over previous
#include <cuda_runtime.h>
#include <cuda_bf16.h>

#define N_NODES 10000
#define N_EDGES 640000
#define D 128

// ---- scratch (no device allocations allowed) ----
__device__ int g_deg[N_NODES];
__device__ int g_off[N_NODES + 1];
__device__ int g_rank[N_EDGES];
__device__ int g_src_sorted[N_EDGES];

// ---------------------------------------------------------------------------
// 1) zero degree histogram (+ pin the sentinel offset)
__global__ void zero_deg_kernel() {
    int i = blockIdx.x * blockDim.x + threadIdx.x;
    if (i < N_NODES) g_deg[i] = 0;
    if (i == 0) g_off[N_NODES] = N_EDGES;
}

// 2) histogram of dst WITH per-edge rank (atomic return value).
//    int4-coalesced loads/stores, 4 independent atomics per thread,
//    160K threads (~34 warps/SM) -> throughput-bound, not latency-bound.
__global__ void rank_hist_kernel(const int* __restrict__ dst) {
    const int T = N_EDGES / 4;  // 160000
    int t = blockIdx.x * blockDim.x + threadIdx.x;
    if (t >= T) return;
    int4 d4 = ((const int4*)dst)[t];
    int r0 = atomicAdd(&g_deg[d4.x], 1);
    int r1 = atomicAdd(&g_deg[d4.y], 1);
    int r2 = atomicAdd(&g_deg[d4.z], 1);
    int r3 = atomicAdd(&g_deg[d4.w], 1);
    ((int4*)g_rank)[t] = make_int4(r0, r1, r2, r3);
}

// 3) single-block exclusive scan (shuffle-based)
__global__ void scan_kernel() {
    __shared__ int warp_sums[32];
    const int t = threadIdx.x;
    const int lane = t & 31, w = t >> 5;
    const int CHUNK = (N_NODES + 1023) / 1024;  // 10
    const int base = t * CHUNK;

    int deg[CHUNK];
    int s = 0;
    #pragma unroll
    for (int i = 0; i < CHUNK; i++) {
        int n = base + i;
        deg[i] = (n < N_NODES) ? g_deg[n] : 0;
        s += deg[i];
    }
    int incl = s;
    #pragma unroll
    for (int d = 1; d < 32; d <<= 1) {
        int v = __shfl_up_sync(0xffffffffu, incl, d);
        if (lane >= d) incl += v;
    }
    if (lane == 31) warp_sums[w] = incl;
    __syncthreads();
    if (w == 0) {
        int iv = warp_sums[lane];
        #pragma unroll
        for (int d = 1; d < 32; d <<= 1) {
            int u = __shfl_up_sync(0xffffffffu, iv, d);
            if (lane >= d) iv += u;
        }
        warp_sums[lane] = iv;
    }
    __syncthreads();
    int run = ((w > 0) ? warp_sums[w - 1] : 0) + (incl - s);
    #pragma unroll
    for (int i = 0; i < CHUNK; i++) {
        int n = base + i;
        if (n < N_NODES) {
            g_off[n] = run;
            run += deg[i];
        }
    }
}

// 4) scatter edges into CSR buckets — NO atomics: pos = off[dst] + rank.
__global__ void scatter_kernel(const int* __restrict__ src,
                               const int* __restrict__ dst) {
    const int T = N_EDGES / 4;
    int t = blockIdx.x * blockDim.x + threadIdx.x;
    if (t >= T) return;
    int4 s4 = ((const int4*)src)[t];
    int4 d4 = ((const int4*)dst)[t];
    int4 r4 = ((const int4*)g_rank)[t];
    int o0 = g_off[d4.x];
    int o1 = g_off[d4.y];
    int o2 = g_off[d4.z];
    int o3 = g_off[d4.w];
    g_src_sorted[o0 + r4.x] = s4.x;
    g_src_sorted[o1 + r4.y] = s4.y;
    g_src_sorted[o2 + r4.z] = s4.z;
    g_src_sorted[o3 + r4.w] = s4.w;
}

// ---------------------------------------------------------------------------
// 5) fused: warp-per-4-nodes gather-sum + register-blocked projection.
//    Gather processes node PAIRS interleaved -> ~64 float4 LDGs in flight
//    per warp (vs 32), covering L2 latency at 16 warps/SM.
#define SW_STRIDE 132
#define SW_FLOATS (D * SW_STRIDE)
#define SH_FLOATS (8 * 4 * D)
#define SMEM_BYTES ((SW_FLOATS + SH_FLOATS) * 4)  // 83968 B
#define NGROUPS (N_NODES / 4)                     // 2500

__device__ __forceinline__ void drain_edges(const float* __restrict__ x,
                                            int e, int e1, int lane,
                                            float4& a0, float4& a1) {
    while (e + 32 <= e1) {
        int idx = g_src_sorted[e + lane];
        #pragma unroll
        for (int j = 0; j < 32; j += 2) {
            int s0 = __shfl_sync(0xffffffffu, idx, j);
            int s1 = __shfl_sync(0xffffffffu, idx, j + 1);
            float4 v0 = *(const float4*)&x[s0 * D + 4 * lane];
            float4 v1 = *(const float4*)&x[s1 * D + 4 * lane];
            a0.x += v0.x; a0.y += v0.y; a0.z += v0.z; a0.w += v0.w;
            a1.x += v1.x; a1.y += v1.y; a1.z += v1.z; a1.w += v1.w;
        }
        e += 32;
    }
    int rem = e1 - e;
    if (rem > 0) {
        int idx = g_src_sorted[e + ((lane < rem) ? lane : 0)];
        for (int j = 0; j < rem; j++) {
            int s = __shfl_sync(0xffffffffu, idx, j);
            float4 v = *(const float4*)&x[s * D + 4 * lane];
            a0.x += v.x; a0.y += v.y; a0.z += v.z; a0.w += v.w;
        }
    }
}

__global__ __launch_bounds__(256)
void fused_agg_proj_kernel(const float* __restrict__ x,
                           const float* __restrict__ W,
                           const float* __restrict__ b,
                           float* __restrict__ out) {
    extern __shared__ float smem[];
    float* sW = smem;                 // [128][132] transposed W
    float* sh = smem + SW_FLOATS;     // [8 warps][4 nodes][128]

    const int tid  = threadIdx.x;
    const int lane = tid & 31;
    const int wid  = tid >> 5;

    // stage W transposed (coalesced gmem reads)
    for (int idx = tid; idx < D * D; idx += 256) {
        int o = idx >> 7;
        int i = idx & 127;
        sW[i * SW_STRIDE + o] = W[idx];
    }
    __syncthreads();

    const int gw = blockIdx.x * 8 + wid;
    if (gw >= NGROUPS) return;

    float* hbuf = &sh[wid * 4 * D];
    const int n0 = gw * 4;

    // ---- gather: 2 node-pairs; within a pair, interleave both edge lists ----
    #pragma unroll
    for (int p = 0; p < 2; p++) {
        const int nA = n0 + 2 * p;
        int eA        = g_off[nA];
        const int eA1 = g_off[nA + 1];
        int eB        = eA1;
        const int eB1 = g_off[nA + 2];

        float4 aA0 = make_float4(0.f, 0.f, 0.f, 0.f);
        float4 aA1 = make_float4(0.f, 0.f, 0.f, 0.f);
        float4 aB0 = make_float4(0.f, 0.f, 0.f, 0.f);
        float4 aB1 = make_float4(0.f, 0.f, 0.f, 0.f);

        while (eA + 32 <= eA1 && eB + 32 <= eB1) {
            int idxA = g_src_sorted[eA + lane];
            int idxB = g_src_sorted[eB + lane];
            #pragma unroll
            for (int j = 0; j < 32; j += 2) {
                int sA0 = __shfl_sync(0xffffffffu, idxA, j);
                int sA1 = __shfl_sync(0xffffffffu, idxA, j + 1);
                int sB0 = __shfl_sync(0xffffffffu, idxB, j);
                int sB1 = __shfl_sync(0xffffffffu, idxB, j + 1);
                float4 vA0 = *(const float4*)&x[sA0 * D + 4 * lane];
                float4 vA1 = *(const float4*)&x[sA1 * D + 4 * lane];
                float4 vB0 = *(const float4*)&x[sB0 * D + 4 * lane];
                float4 vB1 = *(const float4*)&x[sB1 * D + 4 * lane];
                aA0.x += vA0.x; aA0.y += vA0.y; aA0.z += vA0.z; aA0.w += vA0.w;
                aA1.x += vA1.x; aA1.y += vA1.y; aA1.z += vA1.z; aA1.w += vA1.w;
                aB0.x += vB0.x; aB0.y += vB0.y; aB0.z += vB0.z; aB0.w += vB0.w;
                aB1.x += vB1.x; aB1.y += vB1.y; aB1.z += vB1.z; aB1.w += vB1.w;
            }
            eA += 32; eB += 32;
        }
        drain_edges(x, eA, eA1, lane, aA0, aA1);
        drain_edges(x, eB, eB1, lane, aB0, aB1);

        float4 hA = make_float4(aA0.x + aA1.x, aA0.y + aA1.y,
                                aA0.z + aA1.z, aA0.w + aA1.w);
        float4 hB = make_float4(aB0.x + aB1.x, aB0.y + aB1.y,
                                aB0.z + aB1.z, aB0.w + aB1.w);
        *(float4*)&hbuf[(2 * p + 0) * D + 4 * lane] = hA;
        *(float4*)&hbuf[(2 * p + 1) * D + 4 * lane] = hB;
    }
    __syncwarp();

    // ---- projection: 4-node register blocking ----
    const float* hA = &hbuf[0 * D];
    const float* hB = &hbuf[1 * D];
    const float* hC = &hbuf[2 * D];
    const float* hD = &hbuf[3 * D];

    float4 bias = *(const float4*)&b[4 * lane];
    float4 oA = bias, oB = bias, oC = bias, oD = bias;

    #pragma unroll 8
    for (int i4 = 0; i4 < D / 4; i4++) {
        float ha[4], hb_[4], hc[4], hd[4];
        *(float4*)ha  = *(const float4*)&hA[i4 * 4];
        *(float4*)hb_ = *(const float4*)&hB[i4 * 4];
        *(float4*)hc  = *(const float4*)&hC[i4 * 4];
        *(float4*)hd  = *(const float4*)&hD[i4 * 4];
        #pragma unroll
        for (int k = 0; k < 4; k++) {
            float4 w = *(const float4*)&sW[(i4 * 4 + k) * SW_STRIDE + 4 * lane];
            oA.x += ha[k]  * w.x; oA.y += ha[k]  * w.y; oA.z += ha[k]  * w.z; oA.w += ha[k]  * w.w;
            oB.x += hb_[k] * w.x; oB.y += hb_[k] * w.y; oB.z += hb_[k] * w.z; oB.w += hb_[k] * w.w;
            oC.x += hc[k]  * w.x; oC.y += hc[k]  * w.y; oC.z += hc[k]  * w.z; oC.w += hc[k]  * w.w;
            oD.x += hd[k]  * w.x; oD.y += hd[k]  * w.y; oD.z += hd[k]  * w.z; oD.w += hd[k]  * w.w;
        }
    }

    *(float4*)&out[(n0 + 0) * D + 4 * lane] = oA;
    *(float4*)&out[(n0 + 1) * D + 4 * lane] = oB;
    *(float4*)&out[(n0 + 2) * D + 4 * lane] = oC;
    *(float4*)&out[(n0 + 3) * D + 4 * lane] = oD;
}

// ---------------------------------------------------------------------------
extern "C" void kernel_launch(void* const* d_in, const int* in_sizes, int n_in,
                              void* d_out, int out_size) {
    const float* x   = (const float*)d_in[0];
    const int*   src = (const int*)d_in[1];
    const int*   dst = (const int*)d_in[2];
    const float* W   = (const float*)d_in[3];
    const float* b   = (const float*)d_in[4];
    float* out = (float*)d_out;

    cudaFuncSetAttribute(fused_agg_proj_kernel,
                         cudaFuncAttributeMaxDynamicSharedMemorySize,
                         SMEM_BYTES);

    zero_deg_kernel<<<(N_NODES + 255) / 256, 256>>>();
    rank_hist_kernel<<<(N_EDGES / 4 + 255) / 256, 256>>>(dst);
    scan_kernel<<<1, 1024>>>();
    scatter_kernel<<<(N_EDGES / 4 + 255) / 256, 256>>>(src, dst);

    const int blocks = (NGROUPS + 7) / 8;  // 313
    fused_agg_proj_kernel<<<blocks, 256, SMEM_BYTES>>>(x, W, b, out);
}

// round 6
// speedup vs baseline: 2.2867x; 1.0768x over previous
#include <cuda_runtime.h>
#include <cuda_bf16.h>

#define N_NODES 10000
#define N_EDGES 640000
#define D 128
#define NPAIRS (N_NODES / 2)   // 5000 work units of 2 nodes

// ---- scratch (no device allocations allowed) ----
__device__ int g_deg[N_NODES];
__device__ int g_off[N_NODES + 1];
__device__ int g_rank[N_EDGES];
__device__ int g_src_sorted[N_EDGES];
__device__ int g_work;

// ---- f32x2 packed helpers (sm_10x; ptxas won't emit these from C++) ----
__device__ __forceinline__ void fadd2(unsigned long long& acc, unsigned long long v) {
    asm("add.rn.f32x2 %0, %0, %1;" : "+l"(acc) : "l"(v));
}
__device__ __forceinline__ void ffma2(unsigned long long& acc,
                                      unsigned long long a, unsigned long long b) {
    asm("fma.rn.f32x2 %0, %1, %2, %0;" : "+l"(acc) : "l"(a), "l"(b));
}
__device__ __forceinline__ unsigned long long pack2(float h) {
    unsigned long long r;
    asm("mov.b64 %0, {%1, %1};" : "=l"(r) : "f"(h));
    return r;
}

// ---------------------------------------------------------------------------
// 1) zero degree histogram + reset work counter + sentinel offset
__global__ void zero_deg_kernel() {
    int i = blockIdx.x * blockDim.x + threadIdx.x;
    if (i < N_NODES) g_deg[i] = 0;
    if (i == 0) { g_off[N_NODES] = N_EDGES; g_work = 0; }
}

// 2) histogram of dst WITH per-edge rank. ILP 2, 320K threads.
__global__ void rank_hist_kernel(const int* __restrict__ dst) {
    const int T = N_EDGES / 2;  // 320000
    int t = blockIdx.x * blockDim.x + threadIdx.x;
    if (t >= T) return;
    int2 d2 = ((const int2*)dst)[t];
    int r0 = atomicAdd(&g_deg[d2.x], 1);
    int r1 = atomicAdd(&g_deg[d2.y], 1);
    ((int2*)g_rank)[t] = make_int2(r0, r1);
}

// 3) single-block exclusive scan (shuffle-based)
__global__ void scan_kernel() {
    __shared__ int warp_sums[32];
    const int t = threadIdx.x;
    const int lane = t & 31, w = t >> 5;
    const int CHUNK = (N_NODES + 1023) / 1024;  // 10
    const int base = t * CHUNK;

    int deg[CHUNK];
    int s = 0;
    #pragma unroll
    for (int i = 0; i < CHUNK; i++) {
        int n = base + i;
        deg[i] = (n < N_NODES) ? g_deg[n] : 0;
        s += deg[i];
    }
    int incl = s;
    #pragma unroll
    for (int d = 1; d < 32; d <<= 1) {
        int v = __shfl_up_sync(0xffffffffu, incl, d);
        if (lane >= d) incl += v;
    }
    if (lane == 31) warp_sums[w] = incl;
    __syncthreads();
    if (w == 0) {
        int iv = warp_sums[lane];
        #pragma unroll
        for (int d = 1; d < 32; d <<= 1) {
            int u = __shfl_up_sync(0xffffffffu, iv, d);
            if (lane >= d) iv += u;
        }
        warp_sums[lane] = iv;
    }
    __syncthreads();
    int run = ((w > 0) ? warp_sums[w - 1] : 0) + (incl - s);
    #pragma unroll
    for (int i = 0; i < CHUNK; i++) {
        int n = base + i;
        if (n < N_NODES) {
            g_off[n] = run;
            run += deg[i];
        }
    }
}

// 4) scatter edges — no atomics: pos = off[dst] + rank. ILP 2, 320K threads.
__global__ void scatter_kernel(const int* __restrict__ src,
                               const int* __restrict__ dst) {
    const int T = N_EDGES / 2;
    int t = blockIdx.x * blockDim.x + threadIdx.x;
    if (t >= T) return;
    int2 s2 = ((const int2*)src)[t];
    int2 d2 = ((const int2*)dst)[t];
    int2 r2 = ((const int2*)g_rank)[t];
    int o0 = __ldg(&g_off[d2.x]);
    int o1 = __ldg(&g_off[d2.y]);
    g_src_sorted[o0 + r2.x] = s2.x;
    g_src_sorted[o1 + r2.y] = s2.y;
}

// ---------------------------------------------------------------------------
// 5) fused: work-stealing warp-per-2-nodes gather (f32x2 adds) + projection
//    (f32x2 FFMA). 75.8KB smem -> 3 blocks/SM, 24 warps/SM.
#define SW_STRIDE 132
#define SW_FLOATS (D * SW_STRIDE)               // 16896
#define SH_FLOATS (8 * 2 * D)                   // 2048
#define SMEM_BYTES ((SW_FLOATS + SH_FLOATS) * 4)  // 75776 B

__device__ __forceinline__ int steal(int lane) {
    int p = 0;
    if (lane == 0) p = atomicAdd(&g_work, 1);
    return __shfl_sync(0xffffffffu, p, 0);
}

__device__ __forceinline__ void drain_edges(const float* __restrict__ x,
                                            int e, int e1, int lane,
                                            unsigned long long* a0,
                                            unsigned long long* a1) {
    while (e + 32 <= e1) {
        int idx = g_src_sorted[e + lane];
        #pragma unroll
        for (int j = 0; j < 32; j += 2) {
            int s0 = __shfl_sync(0xffffffffu, idx, j);
            int s1 = __shfl_sync(0xffffffffu, idx, j + 1);
            ulonglong2 v0 = *(const ulonglong2*)&x[s0 * D + 4 * lane];
            ulonglong2 v1 = *(const ulonglong2*)&x[s1 * D + 4 * lane];
            fadd2(a0[0], v0.x); fadd2(a0[1], v0.y);
            fadd2(a1[0], v1.x); fadd2(a1[1], v1.y);
        }
        e += 32;
    }
    int rem = e1 - e;
    if (rem > 0) {
        int idx = g_src_sorted[e + ((lane < rem) ? lane : 0)];
        for (int j = 0; j < rem; j++) {
            int s = __shfl_sync(0xffffffffu, idx, j);
            ulonglong2 v = *(const ulonglong2*)&x[s * D + 4 * lane];
            fadd2(a0[0], v.x); fadd2(a0[1], v.y);
        }
    }
}

__global__ __launch_bounds__(256, 3)
void fused_agg_proj_kernel(const float* __restrict__ x,
                           const float* __restrict__ W,
                           const float* __restrict__ b,
                           float* __restrict__ out) {
    extern __shared__ float smem[];
    float* sW = smem;                 // [128][132] transposed W
    float* sh = smem + SW_FLOATS;     // [8 warps][2 nodes][128]

    const int tid  = threadIdx.x;
    const int lane = tid & 31;
    const int wid  = tid >> 5;

    // stage W transposed (coalesced gmem reads)
    for (int idx = tid; idx < D * D; idx += 256) {
        int o = idx >> 7;
        int i = idx & 127;
        sW[i * SW_STRIDE + o] = W[idx];
    }
    __syncthreads();

    float* hbuf = &sh[wid * 2 * D];
    const ulonglong2 bb = *(const ulonglong2*)&b[4 * lane];

    int pair = steal(lane);
    while (pair < NPAIRS) {
        int next = steal(lane);   // prefetch next unit; result used after work

        const int nA = pair * 2;
        int eA        = __ldg(&g_off[nA]);
        const int eA1 = __ldg(&g_off[nA + 1]);
        int eB        = eA1;
        const int eB1 = __ldg(&g_off[nA + 2]);

        unsigned long long aA0[2] = {0ull, 0ull}, aA1[2] = {0ull, 0ull};
        unsigned long long aB0[2] = {0ull, 0ull}, aB1[2] = {0ull, 0ull};

        // interleave both nodes' edge lists for MLP
        while (eA + 32 <= eA1 && eB + 32 <= eB1) {
            int idxA = g_src_sorted[eA + lane];
            int idxB = g_src_sorted[eB + lane];
            #pragma unroll
            for (int j = 0; j < 32; j += 2) {
                int sA0 = __shfl_sync(0xffffffffu, idxA, j);
                int sA1 = __shfl_sync(0xffffffffu, idxA, j + 1);
                int sB0 = __shfl_sync(0xffffffffu, idxB, j);
                int sB1 = __shfl_sync(0xffffffffu, idxB, j + 1);
                ulonglong2 vA0 = *(const ulonglong2*)&x[sA0 * D + 4 * lane];
                ulonglong2 vA1 = *(const ulonglong2*)&x[sA1 * D + 4 * lane];
                ulonglong2 vB0 = *(const ulonglong2*)&x[sB0 * D + 4 * lane];
                ulonglong2 vB1 = *(const ulonglong2*)&x[sB1 * D + 4 * lane];
                fadd2(aA0[0], vA0.x); fadd2(aA0[1], vA0.y);
                fadd2(aA1[0], vA1.x); fadd2(aA1[1], vA1.y);
                fadd2(aB0[0], vB0.x); fadd2(aB0[1], vB0.y);
                fadd2(aB1[0], vB1.x); fadd2(aB1[1], vB1.y);
            }
            eA += 32; eB += 32;
        }
        drain_edges(x, eA, eA1, lane, aA0, aA1);
        drain_edges(x, eB, eB1, lane, aB0, aB1);

        fadd2(aA0[0], aA1[0]); fadd2(aA0[1], aA1[1]);
        fadd2(aB0[0], aB1[0]); fadd2(aB0[1], aB1[1]);
        *(ulonglong2*)&hbuf[0 * D + 4 * lane] = make_ulonglong2(aA0[0], aA0[1]);
        *(ulonglong2*)&hbuf[1 * D + 4 * lane] = make_ulonglong2(aB0[0], aB0[1]);
        __syncwarp();

        // ---- projection: 2-node register blocking, f32x2 FFMA ----
        unsigned long long oA0 = bb.x, oA1 = bb.y;
        unsigned long long oB0 = bb.x, oB1 = bb.y;

        #pragma unroll 4
        for (int i4 = 0; i4 < D / 4; i4++) {
            float ha[4], hb_[4];
            *(float4*)ha  = *(const float4*)&hbuf[0 * D + i4 * 4];  // broadcast
            *(float4*)hb_ = *(const float4*)&hbuf[1 * D + i4 * 4];
            #pragma unroll
            for (int k = 0; k < 4; k++) {
                ulonglong2 w2 = *(const ulonglong2*)&sW[(i4 * 4 + k) * SW_STRIDE + 4 * lane];
                unsigned long long ha2 = pack2(ha[k]);
                unsigned long long hb2 = pack2(hb_[k]);
                ffma2(oA0, ha2, w2.x); ffma2(oA1, ha2, w2.y);
                ffma2(oB0, hb2, w2.x); ffma2(oB1, hb2, w2.y);
            }
        }

        *(ulonglong2*)&out[(nA + 0) * D + 4 * lane] = make_ulonglong2(oA0, oA1);
        *(ulonglong2*)&out[(nA + 1) * D + 4 * lane] = make_ulonglong2(oB0, oB1);
        __syncwarp();

        pair = next;
    }
}

// ---------------------------------------------------------------------------
extern "C" void kernel_launch(void* const* d_in, const int* in_sizes, int n_in,
                              void* d_out, int out_size) {
    const float* x   = (const float*)d_in[0];
    const int*   src = (const int*)d_in[1];
    const int*   dst = (const int*)d_in[2];
    const float* W   = (const float*)d_in[3];
    const float* b   = (const float*)d_in[4];
    float* out = (float*)d_out;

    cudaFuncSetAttribute(fused_agg_proj_kernel,
                         cudaFuncAttributeMaxDynamicSharedMemorySize,
                         SMEM_BYTES);

    zero_deg_kernel<<<(N_NODES + 255) / 256, 256>>>();
    rank_hist_kernel<<<(N_EDGES / 2 + 255) / 256, 256>>>(dst);
    scan_kernel<<<1, 1024>>>();
    scatter_kernel<<<(N_EDGES / 2 + 255) / 256, 256>>>(src, dst);
    fused_agg_proj_kernel<<<444, 256, SMEM_BYTES>>>(x, W, b, out);
}